// round 7
// baseline (speedup 1.0000x reference)
#include <cuda_runtime.h>
#include <cstdint>

#define D_MODEL 1024
#define TPB     256          // each thread owns 4 contiguous channels
#define GRID    296          // 148 SMs x 2 blocks, single fully-resident wave
#define MAX_TOK_PER_BLK 128  // ceil(32768/296)=111; headroom

// ---------------------------------------------------------------------------
// Single fused kernel.
//
// Linear(12->1024) over the polynomial feature map
//   feats = [t^2, t, t+1, t^2, 2t+2, -1, t^2, 0, 2t+1, t^2, 2t+1, 0]
// collapses per output channel d to a quadratic in the token value t:
//   out[tok][d] = A[d]*t^2 + B[d]*t + C[d]
//   A = w0+w3+w6+w9
//   B = w1+w2+2*(w4+w8+w10)
//   C = w2+2*w4-w5+w8+w10 + b
//
// Grid is one fully-resident wave (2 CTAs/SM); each thread computes its 4
// channels' coefficients from W once (48 contiguous floats, 12 L2-hit
// float4 loads; 296 blocks x 48KB = 14MB extra L2 traffic), stages its
// block's tokens in SMEM, then streams 2xFMA + STG.128 rows at the LTS cap.
//
// dtype detection (int64 vs int32 tokens): probe the first 16 odd 32-bit
// words; little-endian int64 values < 32000 have all-zero high halves
// (P(false positive for int32) ~ 32000^-16). Reads stay within the first
// 32 int32 words, valid under either dtype.
// ---------------------------------------------------------------------------
__global__ __launch_bounds__(TPB)
void n2_embed_fused_kernel(const void* __restrict__ ntok_raw,
                           const float* __restrict__ W,
                           const float* __restrict__ b,
                           float4* __restrict__ out,
                           int n_tok) {
    __shared__ float s_t[MAX_TOK_PER_BLK];
    __shared__ int   s_is64;

    const int tid = threadIdx.x;
    const int bid = blockIdx.x;
    const int*  pi  = (const int*)ntok_raw;
    const int2* pi2 = (const int2*)ntok_raw;

    // ---- per-block dtype detection (warp 0, L2-broadcast probes) ----
    if (tid < 32) {
        int probe = (tid < 16) ? pi[2 * tid + 1] : 0;
        unsigned any = __ballot_sync(0xFFFFFFFFu, probe != 0);
        if (tid == 0) s_is64 = (any == 0) ? 1 : 0;
    }

    // ---- balanced contiguous partition of n_tok tokens over the grid ----
    const int grid  = gridDim.x;
    const int q     = n_tok / grid;
    const int rem   = n_tok - q * grid;
    const int base  = q * bid + min(bid, rem);
    const int count = q + (bid < rem ? 1 : 0);

    // ---- per-thread coefficients (48 contiguous floats of W) ----
    const int dbase = tid * 4;
    const float4* Wv = (const float4*)(W + (size_t)dbase * 12);
    const float4 bias = *(const float4*)(b + dbase);

    float A[4], B[4], C[4];
#pragma unroll
    for (int c4 = 0; c4 < 4; c4++) {
        float4 f0 = Wv[3 * c4 + 0];   // w0 w1 w2 w3
        float4 f1 = Wv[3 * c4 + 1];   // w4 w5 w6 w7
        float4 f2 = Wv[3 * c4 + 2];   // w8 w9 w10 w11
        A[c4] = f0.x + f0.w + f1.z + f2.y;                   // w0+w3+w6+w9
        B[c4] = f0.y + f0.z + 2.0f * (f1.x + f2.x + f2.z);   // w1+w2+2(w4+w8+w10)
        C[c4] = f0.z + 2.0f * f1.x - f1.y + f2.x + f2.z;     // +bias below
    }
    C[0] += bias.x; C[1] += bias.y; C[2] += bias.z; C[3] += bias.w;

    __syncthreads();   // s_is64 visible

    // ---- stage this block's tokens into shared (count <= 128 <= TPB) ----
    if (tid < count) {
        int idx = base + tid;
        s_t[tid] = s_is64 ? (float)pi2[idx].x : (float)pi[idx];
    }
    __syncthreads();

    // ---- streaming loop: 2 FMAs + streaming STG.128 per token ----
    const int row_f4 = D_MODEL / 4;  // 256 float4 per token row
    float4* outp = out + (size_t)base * row_f4 + tid;

#pragma unroll 4
    for (int k = 0; k < count; k++) {
        float t = s_t[k];
        float4 o;
        o.x = fmaf(fmaf(A[0], t, B[0]), t, C[0]);
        o.y = fmaf(fmaf(A[1], t, B[1]), t, C[1]);
        o.z = fmaf(fmaf(A[2], t, B[2]), t, C[2]);
        o.w = fmaf(fmaf(A[3], t, B[3]), t, C[3]);
        __stcs(outp, o);          // evict-first: output never re-read
        outp += row_f4;
    }
}

extern "C" void kernel_launch(void* const* d_in, const int* in_sizes, int n_in,
                              void* d_out, int out_size) {
    const void*  ntok = d_in[0];                 // int64 or int32 tokens [B*S]
    const float* W    = (const float*)d_in[1];   // [D_MODEL, 12] row-major
    const float* b    = (const float*)d_in[2];   // [D_MODEL]
    float4* out = (float4*)d_out;

    int n_tok = in_sizes[0];                     // 32768

    n2_embed_fused_kernel<<<GRID, TPB>>>(ntok, W, b, out, n_tok);
}